// round 3
// baseline (speedup 1.0000x reference)
#include <cuda_runtime.h>
#include <math.h>

#define N_NODES 10000
#define N_EDGES 640000
#define IN_C    128
#define HID_C   256
#define OUT_C   128
#define GR_BLOCKS ((N_NODES + 31) / 32)   // 313

// ------------------------- scratch (device globals) -------------------------
__device__ int    g_deg[N_NODES];
__device__ int    g_off[N_NODES + 1];
__device__ int    g_cursor[N_NODES];
__device__ int    g_csr[N_EDGES];
__device__ float  g_dinv[N_NODES];
__device__ float  g_c[N_NODES];            // column sums of normalized adjacency (edge part)
__device__ float  g_y[N_NODES * IN_C];     // (A_hat X)
__device__ float  g_w[HID_C];              // W2 @ fc_w
__device__ double g_part[GR_BLOCKS];       // per-block partial sums

// ------------------------------- kernels ------------------------------------
__global__ void k_init() {
    int i = blockIdx.x * blockDim.x + threadIdx.x;
    if (i < N_NODES) { g_deg[i] = 0; g_c[i] = 0.f; }
}

__global__ void k_count(const int* __restrict__ ei) {
    int e = blockIdx.x * blockDim.x + threadIdx.x;
    if (e < N_EDGES) {
        int dst = ei[N_EDGES + e];
        if ((unsigned)dst < N_NODES) atomicAdd(&g_deg[dst], 1);
    }
}

// single-block exclusive scan over 10000 degrees; also computes dinv
__global__ void k_scan_dinv() {
    __shared__ int sd[1024];
    __shared__ int s_carry;
    int tid = threadIdx.x;
    if (tid == 0) { s_carry = 0; g_off[0] = 0; }
    __syncthreads();
    const int CHUNKS = (N_NODES + 1023) / 1024;
    for (int c = 0; c < CHUNKS; c++) {
        int idx = c * 1024 + tid;
        int v = (idx < N_NODES) ? g_deg[idx] : 0;
        if (idx < N_NODES) g_dinv[idx] = rsqrtf((float)(v + 1)); // +1 self loop
        sd[tid] = v;
        __syncthreads();
        for (int of = 1; of < 1024; of <<= 1) {
            int t = (tid >= of) ? sd[tid - of] : 0;
            __syncthreads();
            sd[tid] += t;
            __syncthreads();
        }
        int incl = sd[tid];
        if (idx < N_NODES) {
            g_off[idx + 1] = s_carry + incl;
            g_cursor[idx]  = s_carry + incl - v;   // exclusive offset
        }
        __syncthreads();
        if (tid == 1023) s_carry += sd[1023];
        __syncthreads();
    }
}

__global__ void k_fill(const int* __restrict__ ei) {
    int e = blockIdx.x * blockDim.x + threadIdx.x;
    if (e < N_EDGES) {
        int src = ei[e];
        int dst = ei[N_EDGES + e];
        if ((unsigned)src < N_NODES && (unsigned)dst < N_NODES) {
            int pos = atomicAdd(&g_cursor[dst], 1);
            g_csr[pos] = src;
            atomicAdd(&g_c[src], g_dinv[src] * g_dinv[dst]);
        }
    }
}

// w = W2 @ fc_w  (W2: [256,128] row-major, fc_w: [128])
__global__ void k_wvec(const float* __restrict__ W2, const float* __restrict__ fcw) {
    int j = threadIdx.x; // 256 threads
    const float4* r = (const float4*)(W2 + j * OUT_C);
    const float4* f = (const float4*)fcw;
    float s = 0.f;
    #pragma unroll
    for (int o = 0; o < OUT_C / 4; o++) {
        float4 a = r[o], b = f[o];
        s += a.x * b.x + a.y * b.y + a.z * b.z + a.w * b.w;
    }
    g_w[j] = s;
}

// y = A_hat @ X : one warp per node, float4 channels
__global__ void k_aggregate(const float* __restrict__ x) {
    int warp = threadIdx.x >> 5, lane = threadIdx.x & 31;
    int n = blockIdx.x * 8 + warp;
    if (n >= N_NODES) return;
    const float4* xb = (const float4*)x; // [N][32]
    float dn = g_dinv[n];
    float4 xs = xb[n * 32 + lane];
    float sl = dn * dn;
    float4 a = make_float4(sl * xs.x, sl * xs.y, sl * xs.z, sl * xs.w);

    int beg = g_off[n], end = g_off[n + 1];
    int j = beg;
    for (; j + 32 <= end; j += 32) {
        int   s  = g_csr[j + lane];
        float nr = g_dinv[s] * dn;
        #pragma unroll
        for (int t = 0; t < 32; t++) {
            int   ss = __shfl_sync(0xffffffffu, s, t);
            float r  = __shfl_sync(0xffffffffu, nr, t);
            float4 xv = xb[ss * 32 + lane];
            a.x += r * xv.x; a.y += r * xv.y; a.z += r * xv.z; a.w += r * xv.w;
        }
    }
    if (j < end) {
        int idx = j + lane;
        int   s  = (idx < end) ? g_csr[idx] : 0;
        float nr = (idx < end) ? g_dinv[s] * dn : 0.f;
        int cnt = end - j;
        for (int t = 0; t < cnt; t++) {
            int   ss = __shfl_sync(0xffffffffu, s, t);
            float r  = __shfl_sync(0xffffffffu, nr, t);
            float4 xv = xb[ss * 32 + lane];
            a.x += r * xv.x; a.y += r * xv.y; a.z += r * xv.z; a.w += r * xv.w;
        }
    }
    ((float4*)g_y)[n * 32 + lane] = a;
}

// fused: H = y @ W1 + b1 ; s[n] = relu(H[n])·w ; partial[b] = sum_n c[n]*s[n]
// block: 256 threads, tile 32 nodes x 256 cols; W1 read through L1 (fits in L1)
__global__ void __launch_bounds__(256) k_gemm_reduce(const float* __restrict__ W1,
                                                     const float* __restrict__ b1) {
    __shared__ float  ys[32 * IN_C];   // 16 KB
    __shared__ double sred[32];

    int tid = threadIdx.x;
    int m0 = blockIdx.x * 32;

    // load y tile (32 x 128), zero-pad past N_NODES
    {
        const float4* y4 = (const float4*)g_y;
        float4* ys4 = (float4*)ys;
        #pragma unroll
        for (int i = tid; i < 32 * IN_C / 4; i += 256) {
            int m = i >> 5;
            int gm = m0 + m;
            ys4[i] = (gm < N_NODES) ? y4[gm * 32 + (i & 31)]
                                    : make_float4(0.f, 0.f, 0.f, 0.f);
        }
    }
    __syncthreads();

    int jg = tid & 31;   // col group (8 cols of 256)
    int mg = tid >> 5;   // warp id -> 4 nodes
    float acc[4][8];
    #pragma unroll
    for (int a = 0; a < 4; a++)
        #pragma unroll
        for (int b = 0; b < 8; b++) acc[a][b] = 0.f;

    const float* y0r = &ys[(mg * 4 + 0) * IN_C];
    const float* y1r = &ys[(mg * 4 + 1) * IN_C];
    const float* y2r = &ys[(mg * 4 + 2) * IN_C];
    const float* y3r = &ys[(mg * 4 + 3) * IN_C];
    const float4* w4 = (const float4*)(W1 + jg * 8);

    #pragma unroll 4
    for (int k = 0; k < IN_C; k++) {
        float yv0 = y0r[k], yv1 = y1r[k], yv2 = y2r[k], yv3 = y3r[k];
        float4 wa = __ldg(&w4[k * (HID_C / 4) + 0]);
        float4 wb = __ldg(&w4[k * (HID_C / 4) + 1]);
        acc[0][0] += yv0 * wa.x; acc[0][1] += yv0 * wa.y; acc[0][2] += yv0 * wa.z; acc[0][3] += yv0 * wa.w;
        acc[0][4] += yv0 * wb.x; acc[0][5] += yv0 * wb.y; acc[0][6] += yv0 * wb.z; acc[0][7] += yv0 * wb.w;
        acc[1][0] += yv1 * wa.x; acc[1][1] += yv1 * wa.y; acc[1][2] += yv1 * wa.z; acc[1][3] += yv1 * wa.w;
        acc[1][4] += yv1 * wb.x; acc[1][5] += yv1 * wb.y; acc[1][6] += yv1 * wb.z; acc[1][7] += yv1 * wb.w;
        acc[2][0] += yv2 * wa.x; acc[2][1] += yv2 * wa.y; acc[2][2] += yv2 * wa.z; acc[2][3] += yv2 * wa.w;
        acc[2][4] += yv2 * wb.x; acc[2][5] += yv2 * wb.y; acc[2][6] += yv2 * wb.z; acc[2][7] += yv2 * wb.w;
        acc[3][0] += yv3 * wa.x; acc[3][1] += yv3 * wa.y; acc[3][2] += yv3 * wa.z; acc[3][3] += yv3 * wa.w;
        acc[3][4] += yv3 * wb.x; acc[3][5] += yv3 * wb.y; acc[3][6] += yv3 * wb.z; acc[3][7] += yv3 * wb.w;
    }

    // epilogue: (acc + b1) -> relu -> dot with w, warp-reduce across col groups
    float bv[8], wv[8];
    *(float4*)&bv[0] = *(const float4*)&b1[jg * 8];
    *(float4*)&bv[4] = *(const float4*)&b1[jg * 8 + 4];
    *(float4*)&wv[0] = *(const float4*)&g_w[jg * 8];
    *(float4*)&wv[4] = *(const float4*)&g_w[jg * 8 + 4];

    double wsum = 0.0;
    #pragma unroll
    for (int mi = 0; mi < 4; mi++) {
        float p = 0.f;
        #pragma unroll
        for (int ji = 0; ji < 8; ji++) {
            float h = acc[mi][ji] + bv[ji];
            h = fmaxf(h, 0.f);
            p += h * wv[ji];
        }
        #pragma unroll
        for (int of = 16; of > 0; of >>= 1) p += __shfl_down_sync(0xffffffffu, p, of);
        if (jg == 0) {
            int n = m0 + mg * 4 + mi;
            if (n < N_NODES) {
                float d = g_dinv[n];
                float cc = g_c[n] + d * d;      // + self-loop column term
                wsum += (double)cc * (double)p;
            }
        }
    }
    if (jg == 0) sred[mg] = wsum;
    __syncthreads();
    if (tid == 0) {
        double s = 0.0;
        #pragma unroll
        for (int i = 0; i < 8; i++) s += sred[i];
        g_part[blockIdx.x] = s;
    }
}

__global__ void k_finalize(const float* __restrict__ b2, const float* __restrict__ fcw,
                           const float* __restrict__ fcb, float* __restrict__ out) {
    __shared__ double dsum[128];
    __shared__ float  fsum[128];
    int tid = threadIdx.x; // 128 threads
    double s = 0.0;
    for (int i = tid; i < GR_BLOCKS; i += 128) s += g_part[i];
    dsum[tid] = s;
    fsum[tid] = b2[tid] * fcw[tid];
    __syncthreads();
    for (int of = 64; of > 0; of >>= 1) {
        if (tid < of) { dsum[tid] += dsum[tid + of]; fsum[tid] += fsum[tid + of]; }
        __syncthreads();
    }
    if (tid == 0) {
        out[0] = (float)(dsum[0] / (double)N_NODES) + fsum[0] + fcb[0];
    }
}

// ------------------------------ launcher ------------------------------------
extern "C" void kernel_launch(void* const* d_in, const int* in_sizes, int n_in,
                              void* d_out, int out_size) {
    const float* x    = (const float*)d_in[0];
    const int*   ei   = (const int*)d_in[1];     // edge_index: int32 (JAX x64 disabled)
    const float* W1   = (const float*)d_in[2];
    const float* b1   = (const float*)d_in[3];
    const float* W2   = (const float*)d_in[4];
    const float* b2   = (const float*)d_in[5];
    const float* fcw  = (const float*)d_in[6];
    const float* fcb  = (const float*)d_in[7];
    float* out = (float*)d_out;

    k_init<<<(N_NODES + 255) / 256, 256>>>();
    k_count<<<(N_EDGES + 255) / 256, 256>>>(ei);
    k_wvec<<<1, HID_C>>>(W2, fcw);
    k_scan_dinv<<<1, 1024>>>();
    k_fill<<<(N_EDGES + 255) / 256, 256>>>(ei);
    k_aggregate<<<(N_NODES + 7) / 8, 256>>>(x);
    k_gemm_reduce<<<GR_BLOCKS, 256>>>(W1, b1);
    k_finalize<<<1, 128>>>(b2, fcw, fcb, out);
}